// round 9
// baseline (speedup 1.0000x reference)
#include <cuda_runtime.h>
#include <cuda_bf16.h>
#include <cstdint>

// Problem constants
#define Bz 8
#define Tz 1024
#define Dz 1024
#define Qz 8
#define Kz 4096
#define dz 128
#define Mz (Bz*Tz)               // 8192 rows
#define OUT_ELEMS (Mz*Dz)        // 8388608
#define IDX_ELEMS (Mz*Qz)        // 65536
#define NQ IDX_ELEMS

#define MARGIN 1.0f
#define CAPT   8                 // slots per (query, group); 8 groups/query -> 64

// Scratch (device globals: allocation-free rule)
__device__ float g_xn[(size_t)Mz*Dz];                    // fp32 normed x (exact rescore)
__device__ float g_hc2[Qz*Kz];                           // 0.5*||c||^2 fp32
__device__ int   g_idx[NQ];
__device__ int   g_cnt[NQ*8];                            // per (query, nh*4+t4)
__device__ int   g_cand[(size_t)NQ*64];
// bf16 operands pre-permuted into HMMA fragment order [frag][lane][16B]
__device__ __align__(16) unsigned char g_xb [(size_t)64*8*32768];   // [mtile][q]: 128x128
__device__ __align__(16) unsigned char g_cbb[(size_t)8*32*32768];   // [q][chunk]: 128x128

static __device__ __forceinline__ void cp16s(uint32_t s, const void* g){
    asm volatile("cp.async.cg.shared.global [%0], [%1], 16;" :: "r"(s), "l"(g));
}
static __device__ __forceinline__ void mma_bf16(float* d, const uint32_t* a, uint32_t b0, uint32_t b1){
    asm volatile("mma.sync.aligned.m16n8k16.row.col.f32.bf16.bf16.f32 "
                 "{%0,%1,%2,%3}, {%4,%5,%6,%7}, {%8,%9}, {%0,%1,%2,%3};"
                 : "+f"(d[0]), "+f"(d[1]), "+f"(d[2]), "+f"(d[3])
                 : "r"(a[0]), "r"(a[1]), "r"(a[2]), "r"(a[3]), "r"(b0), "r"(b1));
}
static __device__ __forceinline__ uint32_t bpack(float x, float y){
    __nv_bfloat162 p = __float22bfloat162_rn(make_float2(x, y));
    return *reinterpret_cast<uint32_t*>(&p);
}

// ---------------- Kernel 1: input rmsnorm (+ fragment-order bf16 write) ----------------
__global__ void rmsnorm_in_kernel(const float* __restrict__ x,
                                  const float* __restrict__ w){
    int m = blockIdx.x, tt = threadIdx.x;
    float4 v = reinterpret_cast<const float4*>(x)[(size_t)m*256 + tt];
    float ss = v.x*v.x + v.y*v.y + v.z*v.z + v.w*v.w;
    __shared__ float sred[8];
    __shared__ float s_scale;
    #pragma unroll
    for (int o = 16; o > 0; o >>= 1) ss += __shfl_xor_sync(0xffffffffu, ss, o);
    if ((tt & 31) == 0) sred[tt >> 5] = ss;
    __syncthreads();
    if (tt < 8){
        float s2 = sred[tt];
        #pragma unroll
        for (int o = 4; o > 0; o >>= 1) s2 += __shfl_xor_sync(0xffu, s2, o);
        if (tt == 0){
            float mean = s2 * (1.0f/1024.0f) + 1e-5f;
            float r = rsqrtf(mean);
            r = r * (1.5f - 0.5f*mean*r*r);
            s_scale = r;
        }
    }
    __syncthreads();
    float sc = s_scale;
    float4 wv = reinterpret_cast<const float4*>(w)[tt];
    float4 o4 = make_float4(v.x*sc*wv.x, v.y*sc*wv.y, v.z*sc*wv.z, v.w*sc*wv.w);
    reinterpret_cast<float4*>(g_xn)[(size_t)m*256 + tt] = o4;

    // A fragment image: region (mtile, q); this thread owns row r=m&127, local k0=(tt&31)*4
    int q  = tt >> 5;
    int k0 = (tt & 31) * 4;
    int r  = m & 127;
    int mf = r >> 4, g = r & 7, hh = (r >> 3) & 1;
    int s  = k0 >> 4;
    int kh = (k0 & 15) >> 3;
    int ta = (k0 & 7) >> 1;                 // in {0,2}; pair B goes to ta+1
    int reg = hh + 2*kh;
    unsigned char* base = g_xb + ((size_t)((m >> 7)*8 + q) << 15);
    uint32_t off = (uint32_t)(((mf*8 + s)*32 + g*4 + ta)*16 + reg*4);
    *reinterpret_cast<uint32_t*>(base + off)      = bpack(o4.x, o4.y);
    *reinterpret_cast<uint32_t*>(base + off + 16) = bpack(o4.z, o4.w);
}

// ---------------- Kernel 2: codebook prep: hc2 + fragment-order bf16 B ----------------
__global__ void cbprep_kernel(const float* __restrict__ cb){
    int code = blockIdx.x*8 + (threadIdx.x >> 5);   // 0..32767
    int lane = threadIdx.x & 31;
    float4 c = reinterpret_cast<const float4*>(cb)[(size_t)code*32 + lane];
    float s = c.x*c.x + c.y*c.y + c.z*c.z + c.w*c.w;
    #pragma unroll
    for (int o = 16; o > 0; o >>= 1) s += __shfl_xor_sync(0xffffffffu, s, o);
    if (lane == 0) g_hc2[code] = 0.5f*s;

    int q = code >> 12, n = code & 4095;
    int ch = n >> 7, nl = n & 127;
    int nf = nl >> 3, g = nl & 7;
    int k0 = lane * 4;
    int sp = k0 >> 5;
    int j  = (k0 & 31) >> 3;
    int ta = (k0 & 7) >> 1;                 // in {0,2}
    unsigned char* base = g_cbb + ((size_t)(q*32 + ch) << 15);
    uint32_t off = (uint32_t)(((nf*4 + sp)*32 + g*4 + ta)*16 + j*4);
    *reinterpret_cast<uint32_t*>(base + off)      = bpack(c.x, c.y);
    *reinterpret_cast<uint32_t*>(base + off + 16) = bpack(c.z, c.w);
}

// ---------------- Kernel 3: HMMA screen + candidate collection ----------------
// Block (mtile, q): 512 threads, 16 warps. Warp tile 16x64: mf = w>>1, nh = w&1.
// 32 chunks of 128 codes. acc = 32 regs/thread (no spills at 128-reg budget).
// Slot ownership per query: 8 groups = nh*4 + t4, CAPT slots each (collision-free).
#define SM_A   0u
#define SM_B0  32768u
#define SM_B1  65536u
#define SM_HC  98304u
#define SMEM_SCREEN 114688

__global__ void __launch_bounds__(512, 1)
screen_kernel(){
    extern __shared__ __align__(16) unsigned char smem[];
    uint32_t sbase = (uint32_t)__cvta_generic_to_shared(smem);

    int tid = threadIdx.x, w = tid >> 5, L = tid & 31;
    int g5 = L >> 2, t4 = L & 3;
    int mf = w >> 1, nh = w & 1;
    int mt = blockIdx.x, q = blockIdx.y, m0 = mt*128;
    int slotbase = (nh*4 + t4)*CAPT;

    // prologue cp.async: A (32KB), hc2 (16KB), B chunk0 (32KB) -> one group
    const unsigned char* gA = g_xb + ((size_t)(mt*8 + q) << 15);
    #pragma unroll
    for (int i = 0; i < 4; ++i)
        cp16s(sbase + SM_A + (uint32_t)(tid + i*512)*16u, gA + (size_t)(tid + i*512)*16);
    const unsigned char* gH = (const unsigned char*)(g_hc2 + q*Kz);
    #pragma unroll
    for (int i = 0; i < 2; ++i)
        cp16s(sbase + SM_HC + (uint32_t)(tid + i*512)*16u, gH + (size_t)(tid + i*512)*16);
    const unsigned char* gB0 = g_cbb + ((size_t)(q*32) << 15);
    #pragma unroll
    for (int i = 0; i < 4; ++i)
        cp16s(sbase + SM_B0 + (uint32_t)(tid + i*512)*16u, gB0 + (size_t)(tid + i*512)*16);
    asm volatile("cp.async.commit_group;");

    // per row-class state: hh in {0,1} -> row = m0 + mf*16 + hh*8 + g5
    float thr[2] = {-3.0e38f, -3.0e38f};
    int   cnt[2] = {0, 0};
    int   gq[2];
    #pragma unroll
    for (int hh = 0; hh < 2; ++hh)
        gq[hh] = (m0 + mf*16 + hh*8 + g5)*Qz + q;

    const float* hcs = (const float*)(smem + SM_HC);

    for (int c = 0; c < 32; ++c){
        __syncthreads();            // everyone done reading buf[(c+1)&1] from iter c-1
        if (c + 1 < 32){
            const unsigned char* gB = g_cbb + ((size_t)(q*32 + c + 1) << 15);
            uint32_t dst = sbase + (((c+1) & 1) ? SM_B1 : SM_B0);
            #pragma unroll
            for (int i = 0; i < 4; ++i)
                cp16s(dst + (uint32_t)(tid + i*512)*16u, gB + (size_t)(tid + i*512)*16);
            asm volatile("cp.async.commit_group;");
            asm volatile("cp.async.wait_group 1;");
        } else {
            asm volatile("cp.async.wait_group 0;");
        }
        __syncthreads();            // B[c] visible to all

        float acc[8][4];
        #pragma unroll
        for (int nf = 0; nf < 8; ++nf)
            #pragma unroll
            for (int r = 0; r < 4; ++r) acc[nf][r] = 0.0f;

        const unsigned char* bb = smem + ((c & 1) ? SM_B1 : SM_B0);
        #pragma unroll
        for (int sp = 0; sp < 4; ++sp){
            uint4 ae = *reinterpret_cast<const uint4*>(smem + SM_A + (((mf*8 + 2*sp    ))*32 + L)*16);
            uint4 ao = *reinterpret_cast<const uint4*>(smem + SM_A + (((mf*8 + 2*sp + 1))*32 + L)*16);
            #pragma unroll
            for (int nf = 0; nf < 8; ++nf){
                uint4 bq = *reinterpret_cast<const uint4*>(bb + (((nh*8+nf)*4 + sp)*32 + L)*16);
                mma_bf16(acc[nf], (const uint32_t*)&ae, bq.x, bq.y);
                mma_bf16(acc[nf], (const uint32_t*)&ao, bq.z, bq.w);
            }
        }

        // refresh thresholds across the quad owning these rows (lag <= 1 chunk: safe)
        #pragma unroll
        for (int hh = 0; hh < 2; ++hh){
            float tv = thr[hh];
            tv = fmaxf(tv, __shfl_xor_sync(0xffffffffu, tv, 1));
            tv = fmaxf(tv, __shfl_xor_sync(0xffffffffu, tv, 2));
            thr[hh] = tv;
        }

        // scan: score = xc - 0.5*||c||^2 ; append candidates near the running max
        const float* hcp = hcs + c*128 + nh*64;
        #pragma unroll
        for (int nf = 0; nf < 8; ++nf){
            float2 hv = *reinterpret_cast<const float2*>(hcp + nf*8 + t4*2);
            int n0 = c*128 + nh*64 + nf*8 + t4*2;
            float v00 = acc[nf][0] - hv.x;   // row hh=0, col n0
            float v01 = acc[nf][1] - hv.y;   // row hh=0, col n0+1
            float v10 = acc[nf][2] - hv.x;   // row hh=1, col n0
            float v11 = acc[nf][3] - hv.y;
            if (v00 > thr[0]){
                if (cnt[0] < CAPT) g_cand[(size_t)gq[0]*64 + slotbase + cnt[0]] = n0;
                cnt[0]++; thr[0] = fmaxf(thr[0], v00 - MARGIN);
            }
            if (v01 > thr[0]){
                if (cnt[0] < CAPT) g_cand[(size_t)gq[0]*64 + slotbase + cnt[0]] = n0 + 1;
                cnt[0]++; thr[0] = fmaxf(thr[0], v01 - MARGIN);
            }
            if (v10 > thr[1]){
                if (cnt[1] < CAPT) g_cand[(size_t)gq[1]*64 + slotbase + cnt[1]] = n0;
                cnt[1]++; thr[1] = fmaxf(thr[1], v10 - MARGIN);
            }
            if (v11 > thr[1]){
                if (cnt[1] < CAPT) g_cand[(size_t)gq[1]*64 + slotbase + cnt[1]] = n0 + 1;
                cnt[1]++; thr[1] = fmaxf(thr[1], v11 - MARGIN);
            }
        }
    }

    #pragma unroll
    for (int hh = 0; hh < 2; ++hh)
        g_cnt[(size_t)gq[hh]*8 + nh*4 + t4] = cnt[hh];
}

// ---------------- Kernel 4: exact fp32 rescore of candidates ----------------
__global__ void resolve_kernel(const float* __restrict__ cb, float* __restrict__ tail){
    int gw = blockIdx.x*8 + (threadIdx.x >> 5);     // query id 0..65535
    int lane = threadIdx.x & 31;
    int m = gw >> 3, q = gw & 7;
    float4 xv = reinterpret_cast<const float4*>(g_xn + (size_t)m*Dz + q*dz)[lane];
    int4 ca = *reinterpret_cast<const int4*>(g_cnt + (size_t)gw*8);
    int4 cb4 = *reinterpret_cast<const int4*>(g_cnt + (size_t)gw*8 + 4);
    const float* hq = g_hc2 + q*Kz;
    const float4* cbq = reinterpret_cast<const float4*>(cb + (size_t)q*Kz*dz);
    float bv = -3.4e38f; int bi = 0;
    int cc[8] = {ca.x, ca.y, ca.z, ca.w, cb4.x, cb4.y, cb4.z, cb4.w};
    bool ok = true;
    #pragma unroll
    for (int t = 0; t < 8; ++t) ok = ok && (cc[t] <= CAPT);

    if (ok){
        #pragma unroll
        for (int t = 0; t < 8; ++t){
            for (int i = 0; i < cc[t]; ++i){
                int n = g_cand[(size_t)gw*64 + t*CAPT + i];
                float4 cv = cbq[(size_t)n*32 + lane];
                float p = xv.x*cv.x + xv.y*cv.y + xv.z*cv.z + xv.w*cv.w;
                #pragma unroll
                for (int o = 16; o > 0; o >>= 1) p += __shfl_xor_sync(0xffffffffu, p, o);
                float s = p - hq[n];
                if (s > bv || (s == bv && n < bi)) { bv = s; bi = n; }
            }
        }
    } else {
        // overflow fallback: brute force all codes (rare)
        for (int n = 0; n < Kz; ++n){
            float4 cv = cbq[(size_t)n*32 + lane];
            float p = xv.x*cv.x + xv.y*cv.y + xv.z*cv.z + xv.w*cv.w;
            #pragma unroll
            for (int o = 16; o > 0; o >>= 1) p += __shfl_xor_sync(0xffffffffu, p, o);
            float s = p - hq[n];
            if (s > bv) { bv = s; bi = n; }
        }
    }
    if (lane == 0){
        g_idx[gw] = bi;
        if (tail) tail[gw] = (float)bi;
    }
}

// ---------------- Kernel 5: gather codes + output rmsnorm ----------------
__global__ void out_kernel(const float* __restrict__ cb,
                           const float* __restrict__ w,
                           float* __restrict__ out){
    int m = blockIdx.x, t = threadIdx.x;
    __shared__ int   sidx[8];
    __shared__ float s_scale;
    if (t < 8) sidx[t] = g_idx[m*Qz + t];
    __syncthreads();
    if (t < 8){
        float p = g_hc2[t*Kz + sidx[t]];
        #pragma unroll
        for (int o = 4; o > 0; o >>= 1) p += __shfl_xor_sync(0xffu, p, o);
        if (t == 0){
            float mean = (2.0f*p) * (1.0f/1024.0f) + 1e-5f;
            float r = rsqrtf(mean);
            r = r * (1.5f - 0.5f*mean*r*r);
            s_scale = r;
        }
    }
    __syncthreads();
    int q = t >> 5, lane = t & 31;
    float4 c = reinterpret_cast<const float4*>(cb)[((size_t)q*Kz + sidx[q])*32 + lane];
    float sc = s_scale;
    float4 wv = reinterpret_cast<const float4*>(w)[t];
    reinterpret_cast<float4*>(out)[(size_t)m*256 + t] =
        make_float4(c.x*sc*wv.x, c.y*sc*wv.y, c.z*sc*wv.z, c.w*sc*wv.w);
}

// ---------------- Launch ----------------
extern "C" void kernel_launch(void* const* d_in, const int* in_sizes, int n_in,
                              void* d_out, int out_size){
    const float* x     = (const float*)d_in[0];
    const float* cb    = (const float*)d_in[1];
    const float* w_in  = (const float*)d_in[2];
    const float* w_out = (const float*)d_in[3];
    float* out = (float*)d_out;
    float* tail = (out_size >= OUT_ELEMS + IDX_ELEMS) ? (out + OUT_ELEMS) : nullptr;

    cudaFuncSetAttribute((const void*)screen_kernel,
                         cudaFuncAttributeMaxDynamicSharedMemorySize, SMEM_SCREEN);

    rmsnorm_in_kernel<<<Mz, 256>>>(x, w_in);
    cbprep_kernel<<<(Qz*Kz)/8, 256>>>(cb);
    screen_kernel<<<dim3(64, 8), 512, SMEM_SCREEN>>>();
    resolve_kernel<<<NQ/8, 256>>>(cb, tail);
    out_kernel<<<Mz, 256>>>(cb, w_out, out);
}

// round 10
// speedup vs baseline: 2.6505x; 2.6505x over previous
#include <cuda_runtime.h>
#include <cstdint>

// Problem constants
#define Bz 8
#define Tz 1024
#define Dz 1024
#define Qz 8
#define Kz 4096
#define dz 128
#define Mz (Bz*Tz)               // 8192 rows
#define OUT_ELEMS (Mz*Dz)        // 8388608
#define IDX_ELEMS (Mz*Qz)        // 65536

// Scratch (device globals: allocation-free rule)
__device__ float g_xn[(size_t)Mz*Dz];        // rmsnorm'd input (row-major)
__device__ float g_hc2[Qz*Kz];               // 0.5 * ||code||^2
__device__ float g_cbt[(size_t)Qz*dz*Kz];    // codebook transposed [q][k][n], 16MB
__device__ int   g_idx[Mz*Qz];               // argmin indices

// ---- f32x2 packed-FMA helpers (sm_103a FFMA2) ----
static __device__ __forceinline__ unsigned long long pack2(float v){
    unsigned long long r; unsigned u = __float_as_uint(v);
    asm("mov.b64 %0, {%1, %1};" : "=l"(r) : "r"(u));
    return r;
}
static __device__ __forceinline__ void ffma2(unsigned long long& d,
                                             unsigned long long a,
                                             unsigned long long b){
    asm("fma.rn.f32x2 %0, %1, %2, %0;" : "+l"(d) : "l"(a), "l"(b));
}
static __device__ __forceinline__ float2 unpack2(unsigned long long v){
    unsigned lo, hi;
    asm("mov.b64 {%0, %1}, %2;" : "=r"(lo), "=r"(hi) : "l"(v));
    return make_float2(__uint_as_float(lo), __uint_as_float(hi));
}
static __device__ __forceinline__ void cp16(uint32_t s, const float* g){
    asm volatile("cp.async.cg.shared.global [%0], [%1], 16;" :: "r"(s), "l"(g));
}

// ---------------- Kernel 1: input rmsnorm ----------------
__global__ void rmsnorm_in_kernel(const float* __restrict__ x,
                                  const float* __restrict__ w){
    int m = blockIdx.x, t = threadIdx.x;
    float4 v = reinterpret_cast<const float4*>(x)[(size_t)m*256 + t];
    float ss = v.x*v.x + v.y*v.y + v.z*v.z + v.w*v.w;
    __shared__ float sred[8];
    __shared__ float s_scale;
    #pragma unroll
    for (int o = 16; o > 0; o >>= 1) ss += __shfl_xor_sync(0xffffffffu, ss, o);
    if ((t & 31) == 0) sred[t >> 5] = ss;
    __syncthreads();
    if (t < 8){
        float s2 = sred[t];
        #pragma unroll
        for (int o = 4; o > 0; o >>= 1) s2 += __shfl_xor_sync(0xffu, s2, o);
        if (t == 0){
            float mean = s2 * (1.0f/1024.0f) + 1e-5f;
            float r = rsqrtf(mean);
            r = r * (1.5f - 0.5f*mean*r*r);   // one Newton step
            s_scale = r;
        }
    }
    __syncthreads();
    float sc = s_scale;
    float4 wv = reinterpret_cast<const float4*>(w)[t];
    float4 o4 = make_float4(v.x*sc*wv.x, v.y*sc*wv.y, v.z*sc*wv.z, v.w*sc*wv.w);
    reinterpret_cast<float4*>(g_xn)[(size_t)m*256 + t] = o4;
}

// ---------------- Kernel 2: 0.5*||code||^2 + transposed codebook ----------------
__global__ void cbprep_kernel(const float* __restrict__ cb){
    int code = blockIdx.x*8 + (threadIdx.x >> 5);   // 0..32767
    int lane = threadIdx.x & 31;
    float4 c = reinterpret_cast<const float4*>(cb)[(size_t)code*32 + lane];
    float s = c.x*c.x + c.y*c.y + c.z*c.z + c.w*c.w;
    #pragma unroll
    for (int o = 16; o > 0; o >>= 1) s += __shfl_xor_sync(0xffffffffu, s, o);
    if (lane == 0) g_hc2[code] = 0.5f*s;

    int q = code >> 12, n = code & 4095;
    float* dst = g_cbt + ((size_t)q*dz + 4*lane)*Kz + n;
    dst[0]      = c.x;
    dst[Kz]     = c.y;
    dst[2*Kz]   = c.z;
    dst[3*(size_t)Kz] = c.w;
}

// ---------------- Kernel 3: fused GEMM + argmax(xc - 0.5c2) ----------------
// Tile: 32 rows x 512-col chunks (8 chunks). 256 thr = 4 ty x 64 tx; microtile 8x8.
// Thread cols: txh*128 + 4*tx4 + {0..3} and +64 (conflict-free 16B-lane-stride LDS).
// A resident full-k in smem (transposed); B double-buffered kc=16 via cp.async
// from the pre-transposed g_cbt. 2048 tasks -> 98.8% slot utilization.
#define SA2   36                   // As row stride (words), 16B-aligned, pad 4
#define BST2  516                  // B k-row stride (words), 16B-aligned, pad 4
#define KC    16
#define NSTG  64                   // 128k/16 per chunk * 8 chunks
#define SMEM_ARGMIN ((128*SA2 + 2*KC*BST2)*4)   // 18432 + 66048 = 84480

__global__ void __launch_bounds__(256, 2)
argmin_kernel(float* __restrict__ tail){
    extern __shared__ float sm[];
    float* As = sm;                  // [k 128][row 32 (+pad)]
    float* B0 = sm + 128*SA2;        // [k 16][col 512 (+pad)]
    float* B1 = B0 + KC*BST2;

    int tid = threadIdx.x;
    int tx = tid & 63, ty = tid >> 6;
    int tx4 = tx & 15, txh = tx >> 4;
    int q  = blockIdx.y;
    int m0 = blockIdx.x * 32;

    const float* xq  = g_xn + (size_t)m0*Dz + q*dz;
    const float* cbt = g_cbt + (size_t)q*dz*Kz;
    const float* hcq = g_hc2 + q*Kz;

    uint32_t sbB = (uint32_t)__cvta_generic_to_shared(B0);

    // ---- A tile: 32 rows x 128 k, transposed As[k][row]. One-time load.
    #pragma unroll
    for (int it = 0; it < 4; ++it){
        int u  = it*256 + tid;
        int kk = u >> 3;            // 0..127
        int rg = u & 7;             // 4-row group 0..7
        const float* p = xq + (size_t)(4*rg)*Dz + kk;
        float a0 = p[0], a1 = p[Dz], a2 = p[2*Dz], a3 = p[3*(size_t)Dz];
        *reinterpret_cast<float4*>(&As[kk*SA2 + 4*rg]) = make_float4(a0,a1,a2,a3);
    }

    // ---- stage s = chunk(s>>3)*8 + kc(s&7); cp 16 k-rows x 512 cols.
    // prologue: stage 0
    {
        const float* src = cbt;     // chunk 0, k0 = 0
        #pragma unroll
        for (int i = 0; i < 8; ++i){
            int u  = tid + i*256;   // 0..2047
            int kk = u >> 7;        // 0..15
            int o  = u & 127;       // 16B unit along cols
            cp16(sbB + (uint32_t)(kk*BST2 + o*4)*4u, src + (size_t)kk*Kz + o*4);
        }
        asm volatile("cp.async.commit_group;");
    }

    unsigned long long acc[4][8];   // [row-pair p][col j]; rows 8ty+2p, 8ty+2p+1
    float bestv[8];
    int   besti[8];
    #pragma unroll
    for (int i = 0; i < 8; ++i){ bestv[i] = -3.4e38f; besti[i] = 0; }

    for (int s = 0; s < NSTG; ++s){
        // prefetch next stage into the other buffer (its last reads closed
        // by the end-of-iteration sync of stage s-1)
        if (s + 1 < NSTG){
            int cn = (s+1) >> 3, k0n = ((s+1) & 7)*16;
            const float* src = cbt + (size_t)k0n*Kz + cn*512;
            uint32_t dst = sbB + (uint32_t)(((s+1) & 1)*KC*BST2)*4u;
            #pragma unroll
            for (int i = 0; i < 8; ++i){
                int u  = tid + i*256;
                int kk = u >> 7;
                int o  = u & 127;
                cp16(dst + (uint32_t)(kk*BST2 + o*4)*4u, src + (size_t)kk*Kz + o*4);
            }
            asm volatile("cp.async.commit_group;");
            asm volatile("cp.async.wait_group 1;");
        } else {
            asm volatile("cp.async.wait_group 0;");
        }
        __syncthreads();            // stage s published to all threads

        int c = s >> 3, kc = s & 7;

        // chunk start: acc <- -0.5*||c||^2 (argmax form)
        if (kc == 0){
            int nb = c*512 + txh*128 + 4*tx4;
            float4 h0 = *reinterpret_cast<const float4*>(hcq + nb);
            float4 h1 = *reinterpret_cast<const float4*>(hcq + nb + 64);
            unsigned long long hp[8];
            hp[0]=pack2(-h0.x); hp[1]=pack2(-h0.y); hp[2]=pack2(-h0.z); hp[3]=pack2(-h0.w);
            hp[4]=pack2(-h1.x); hp[5]=pack2(-h1.y); hp[6]=pack2(-h1.z); hp[7]=pack2(-h1.w);
            #pragma unroll
            for (int p = 0; p < 4; ++p)
                #pragma unroll
                for (int j = 0; j < 8; ++j) acc[p][j] = hp[j];
        }

        const float* Bs = (s & 1) ? B1 : B0;
        const float* Ab = As + kc*16*SA2 + 8*ty;
        const float* Bb = Bs + txh*128 + 4*tx4;

        #pragma unroll
        for (int k = 0; k < 16; ++k){
            ulonglong2 a0 = *reinterpret_cast<const ulonglong2*>(Ab + k*SA2);      // rows 0-3
            ulonglong2 a1 = *reinterpret_cast<const ulonglong2*>(Ab + k*SA2 + 4);  // rows 4-7
            float4 b0 = *reinterpret_cast<const float4*>(Bb + k*BST2);
            float4 b1 = *reinterpret_cast<const float4*>(Bb + k*BST2 + 64);
            unsigned long long bb0 = pack2(b0.x), bb1 = pack2(b0.y);
            unsigned long long bb2 = pack2(b0.z), bb3 = pack2(b0.w);
            unsigned long long bb4 = pack2(b1.x), bb5 = pack2(b1.y);
            unsigned long long bb6 = pack2(b1.z), bb7 = pack2(b1.w);
            ffma2(acc[0][0], a0.x, bb0); ffma2(acc[1][0], a0.y, bb0);
            ffma2(acc[2][0], a1.x, bb0); ffma2(acc[3][0], a1.y, bb0);
            ffma2(acc[0][1], a0.x, bb1); ffma2(acc[1][1], a0.y, bb1);
            ffma2(acc[2][1], a1.x, bb1); ffma2(acc[3][1], a1.y, bb1);
            ffma2(acc[0][2], a0.x, bb2); ffma2(acc[1][2], a0.y, bb2);
            ffma2(acc[2][2], a1.x, bb2); ffma2(acc[3][2], a1.y, bb2);
            ffma2(acc[0][3], a0.x, bb3); ffma2(acc[1][3], a0.y, bb3);
            ffma2(acc[2][3], a1.x, bb3); ffma2(acc[3][3], a1.y, bb3);
            ffma2(acc[0][4], a0.x, bb4); ffma2(acc[1][4], a0.y, bb4);
            ffma2(acc[2][4], a1.x, bb4); ffma2(acc[3][4], a1.y, bb4);
            ffma2(acc[0][5], a0.x, bb5); ffma2(acc[1][5], a0.y, bb5);
            ffma2(acc[2][5], a1.x, bb5); ffma2(acc[3][5], a1.y, bb5);
            ffma2(acc[0][6], a0.x, bb6); ffma2(acc[1][6], a0.y, bb6);
            ffma2(acc[2][6], a1.x, bb6); ffma2(acc[3][6], a1.y, bb6);
            ffma2(acc[0][7], a0.x, bb7); ffma2(acc[1][7], a0.y, bb7);
            ffma2(acc[2][7], a1.x, bb7); ffma2(acc[3][7], a1.y, bb7);
        }

        // chunk end: fold acc into running argmax (strict > keeps lowest idx;
        // per-thread col visit order is ascending)
        if (kc == 7){
            int nb = c*512 + txh*128 + 4*tx4;
            #pragma unroll
            for (int p = 0; p < 4; ++p)
                #pragma unroll
                for (int j = 0; j < 8; ++j){
                    int n = (j < 4) ? (nb + j) : (nb + 64 + j - 4);
                    float2 v = unpack2(acc[p][j]);
                    if (v.x > bestv[2*p])   { bestv[2*p]   = v.x; besti[2*p]   = n; }
                    if (v.y > bestv[2*p+1]) { bestv[2*p+1] = v.y; besti[2*p+1] = n; }
                }
        }
        __syncthreads();            // close stage s reads before next prefetch
    }

    // Cross-thread reduction: 64 tx candidates per row; max, tie -> lower idx
    float* rv = sm;                                    // 32*64 floats (8KB)
    int*   ri = reinterpret_cast<int*>(sm + 32*64);    // 32*64 ints  (8KB)
    #pragma unroll
    for (int i = 0; i < 8; ++i){
        int row = ty*8 + i;
        rv[row*64 + tx] = bestv[i];
        ri[row*64 + tx] = besti[i];
    }
    __syncthreads();
    if (tid < 32){
        float bv = rv[tid*64]; int bi = ri[tid*64];
        #pragma unroll 8
        for (int t2 = 1; t2 < 64; ++t2){
            float v = rv[tid*64 + t2]; int id = ri[tid*64 + t2];
            if (v > bv || (v == bv && id < bi)) { bv = v; bi = id; }
        }
        int m = m0 + tid;
        g_idx[m*Qz + q] = bi;
        if (tail) tail[m*Qz + q] = (float)bi;
    }
}

// ---------------- Kernel 4: gather codes + output rmsnorm ----------------
__global__ void out_kernel(const float* __restrict__ cb,
                           const float* __restrict__ w,
                           float* __restrict__ out){
    int m = blockIdx.x, t = threadIdx.x;
    __shared__ int   sidx[8];
    __shared__ float s_scale;
    if (t < 8) sidx[t] = g_idx[m*Qz + t];
    __syncthreads();
    if (t < 8){
        float p = g_hc2[t*Kz + sidx[t]];
        #pragma unroll
        for (int o = 4; o > 0; o >>= 1) p += __shfl_xor_sync(0xffu, p, o);
        if (t == 0){
            float mean = (2.0f*p) * (1.0f/1024.0f) + 1e-5f;
            float r = rsqrtf(mean);
            r = r * (1.5f - 0.5f*mean*r*r);
            s_scale = r;
        }
    }
    __syncthreads();
    int q = t >> 5, lane = t & 31;
    float4 c = reinterpret_cast<const float4*>(cb)[((size_t)q*Kz + sidx[q])*32 + lane];
    float sc = s_scale;
    float4 wv = reinterpret_cast<const float4*>(w)[t];
    reinterpret_cast<float4*>(out)[(size_t)m*256 + t] =
        make_float4(c.x*sc*wv.x, c.y*sc*wv.y, c.z*sc*wv.z, c.w*sc*wv.w);
}

// ---------------- Launch ----------------
extern "C" void kernel_launch(void* const* d_in, const int* in_sizes, int n_in,
                              void* d_out, int out_size){
    const float* x     = (const float*)d_in[0];
    const float* cb    = (const float*)d_in[1];
    const float* w_in  = (const float*)d_in[2];
    const float* w_out = (const float*)d_in[3];
    float* out = (float*)d_out;
    float* tail = (out_size >= OUT_ELEMS + IDX_ELEMS) ? (out + OUT_ELEMS) : nullptr;

    cudaFuncSetAttribute((const void*)argmin_kernel,
                         cudaFuncAttributeMaxDynamicSharedMemorySize, SMEM_ARGMIN);

    rmsnorm_in_kernel<<<Mz, 256>>>(x, w_in);
    cbprep_kernel<<<(Qz*Kz)/8, 256>>>(cb);
    argmin_kernel<<<dim3(Mz/32, Qz), 256, SMEM_ARGMIN>>>(tail);
    out_kernel<<<Mz, 256>>>(cb, w_out, out);
}

// round 11
// speedup vs baseline: 3.1066x; 1.1721x over previous
#include <cuda_runtime.h>
#include <cstdint>

// Problem constants
#define Bz 8
#define Tz 1024
#define Dz 1024
#define Qz 8
#define Kz 4096
#define dz 128
#define Mz (Bz*Tz)               // 8192 rows
#define OUT_ELEMS (Mz*Dz)        // 8388608
#define IDX_ELEMS (Mz*Qz)        // 65536

// Scratch (device globals: allocation-free rule)
__device__ float  g_xn[(size_t)Mz*Dz];        // rmsnorm'd input, 32MB
__device__ float  g_hc2[Qz*Kz];               // 0.5 * ||code||^2
__device__ float2 g_pb[(size_t)Mz*Qz*4];      // per-quarter partial (val, idx-bits)

// ---- f32x2 packed-FMA helpers (sm_103a FFMA2) ----
static __device__ __forceinline__ unsigned long long pack2(float v){
    unsigned long long r; unsigned u = __float_as_uint(v);
    asm("mov.b64 %0, {%1, %1};" : "=l"(r) : "r"(u));
    return r;
}
static __device__ __forceinline__ void ffma2(unsigned long long& d,
                                             unsigned long long a,
                                             unsigned long long b){
    asm("fma.rn.f32x2 %0, %1, %2, %0;" : "+l"(d) : "l"(a), "l"(b));
}
static __device__ __forceinline__ float2 unpack2(unsigned long long v){
    unsigned lo, hi;
    asm("mov.b64 {%0, %1}, %2;" : "=r"(lo), "=r"(hi) : "l"(v));
    return make_float2(__uint_as_float(lo), __uint_as_float(hi));
}

// ---------------- Kernel 1: input rmsnorm ----------------
__global__ void rmsnorm_in_kernel(const float* __restrict__ x,
                                  const float* __restrict__ w){
    int m = blockIdx.x, t = threadIdx.x;
    float4 v = reinterpret_cast<const float4*>(x)[(size_t)m*256 + t];
    float ss = v.x*v.x + v.y*v.y + v.z*v.z + v.w*v.w;
    __shared__ float sred[8];
    __shared__ float s_scale;
    #pragma unroll
    for (int o = 16; o > 0; o >>= 1) ss += __shfl_xor_sync(0xffffffffu, ss, o);
    if ((t & 31) == 0) sred[t >> 5] = ss;
    __syncthreads();
    if (t < 8){
        float s2 = sred[t];
        #pragma unroll
        for (int o = 4; o > 0; o >>= 1) s2 += __shfl_xor_sync(0xffu, s2, o);
        if (t == 0){
            float mean = s2 * (1.0f/1024.0f) + 1e-5f;
            float r = rsqrtf(mean);
            r = r * (1.5f - 0.5f*mean*r*r);   // one Newton step
            s_scale = r;
        }
    }
    __syncthreads();
    float sc = s_scale;
    float4 wv = reinterpret_cast<const float4*>(w)[t];
    float4 o4 = make_float4(v.x*sc*wv.x, v.y*sc*wv.y, v.z*sc*wv.z, v.w*sc*wv.w);
    reinterpret_cast<float4*>(g_xn)[(size_t)m*256 + t] = o4;
}

// ---------------- Kernel 2: 0.5 * ||code||^2 ----------------
__global__ void hc2_kernel(const float* __restrict__ cb){
    int code = blockIdx.x*8 + (threadIdx.x >> 5);
    int lane = threadIdx.x & 31;
    float4 c = reinterpret_cast<const float4*>(cb)[(size_t)code*32 + lane];
    float s = c.x*c.x + c.y*c.y + c.z*c.z + c.w*c.w;
    #pragma unroll
    for (int o = 16; o > 0; o >>= 1) s += __shfl_xor_sync(0xffffffffu, s, o);
    if (lane == 0) g_hc2[code] = 0.5f*s;
}

// ---------------- Kernel 3: fused GEMM + argmax(xc - 0.5c2), col-quartered ----
// Block = (128-row mtile, 1024-col quarter, q): blockIdx.x = mt*4 + qt.
// 2048 tasks of tau/4 -> 7 waves on 296 slots = 1.75tau (vs 2tau at R3).
// Microkernel identical to R3 (8x8 f32x2 outer product, broadcast A,
// reg-staged double-buffered B). Writes per-quarter partial argmax.
#define SA   132                   // As row-dim stride (words); STS conflict-free
#define BSTR 192                   // B k-row stride (words); 16 groups * 12
#define SMEM_ARGMIN (128*SA*4 + 2*16*BSTR*4)   // 67584 + 24576 = 92160

static __device__ __forceinline__ int bcol(int c){ return 12*(c>>3) + (c&7); }

__global__ void __launch_bounds__(256, 2)
argmin_kernel(const float* __restrict__ cb){
    extern __shared__ float sm[];
    float* As = sm;
    float* B0 = sm + 128*SA;
    float* B1 = B0 + 16*BSTR;

    int tid = threadIdx.x;
    int tx = tid & 15, ty = tid >> 4;
    int q  = blockIdx.y;
    int bx = blockIdx.x;
    int mt = bx >> 2, qt = bx & 3;
    int m0 = mt*128;
    int qb = qt*1024;                                  // column-quarter base

    const float* xq  = g_xn + (size_t)m0*Dz + q*dz;
    const float* cbq = cb + (size_t)q*Kz*dz + (size_t)qb*dz;
    const float* hcq = g_hc2 + q*Kz + qb;

    // ---- A tile: 128 rows x 128 k, transposed As[k][row]. One-time load.
    #pragma unroll
    for (int it = 0; it < 16; ++it){
        int u  = it*256 + tid;
        int kk = (u & 31) + ((u >> 10) << 5);
        int rg = (u >> 5) & 31;
        const float* p = xq + (size_t)(4*rg)*Dz + kk;
        float a0 = p[0], a1 = p[Dz], a2 = p[2*Dz], a3 = p[3*Dz];
        *reinterpret_cast<float4*>(&As[kk*SA + 4*rg]) = make_float4(a0,a1,a2,a3);
    }

    // per-thread B staging: 2 float4 per iteration (128 cols x 16 k / 256 thr)
    int pks0 = tid & 3,         pcol0 = tid >> 2;
    int pks1 = (256+tid) & 3,   pcol1 = (256+tid) >> 2;
    int bc0 = bcol(pcol0), bc1 = bcol(pcol1);

    // prologue: load + store B for iteration 0 into B0
    float4 pre0 = *reinterpret_cast<const float4*>(cbq + (size_t)pcol0*dz + 4*pks0);
    float4 pre1 = *reinterpret_cast<const float4*>(cbq + (size_t)pcol1*dz + 4*pks1);
    B0[(4*pks0+0)*BSTR + bc0] = pre0.x;  B0[(4*pks0+1)*BSTR + bc0] = pre0.y;
    B0[(4*pks0+2)*BSTR + bc0] = pre0.z;  B0[(4*pks0+3)*BSTR + bc0] = pre0.w;
    B0[(4*pks1+0)*BSTR + bc1] = pre1.x;  B0[(4*pks1+1)*BSTR + bc1] = pre1.y;
    B0[(4*pks1+2)*BSTR + bc1] = pre1.z;  B0[(4*pks1+3)*BSTR + bc1] = pre1.w;
    __syncthreads();

    unsigned long long acc[4][8];    // [row-pair][col]; rows 8*ty+2p, 8*ty+2p+1
    float bestv[8];
    int   besti[8];
    #pragma unroll
    for (int i = 0; i < 8; ++i){ bestv[i] = -3.4e38f; besti[i] = 0; }

    for (int it = 0; it < 64; ++it){            // it = chunk*8 + kc ; 8 chunks of 128 cols
        int c = it >> 3, kc = it & 7;

        // prefetch next B sub-tile into registers (hidden under compute)
        if (it + 1 < 64){
            int nc = (it+1) >> 3, nkc = (it+1) & 7;
            const float* bg = cbq + (size_t)nc*128*dz + nkc*16;
            pre0 = *reinterpret_cast<const float4*>(bg + (size_t)pcol0*dz + 4*pks0);
            pre1 = *reinterpret_cast<const float4*>(bg + (size_t)pcol1*dz + 4*pks1);
        }

        // chunk start: acc <- -0.5*||c||^2 (argmax form)
        if (kc == 0){
            float4 h0 = *reinterpret_cast<const float4*>(hcq + c*128 + 8*tx);
            float4 h1 = *reinterpret_cast<const float4*>(hcq + c*128 + 8*tx + 4);
            unsigned long long hp[8];
            hp[0]=pack2(-h0.x); hp[1]=pack2(-h0.y); hp[2]=pack2(-h0.z); hp[3]=pack2(-h0.w);
            hp[4]=pack2(-h1.x); hp[5]=pack2(-h1.y); hp[6]=pack2(-h1.z); hp[7]=pack2(-h1.w);
            #pragma unroll
            for (int p = 0; p < 4; ++p)
                #pragma unroll
                for (int j = 0; j < 8; ++j) acc[p][j] = hp[j];
        }

        const float* Bc = (it & 1) ? B1 : B0;
        const float* Ab = As + (kc*16)*SA + 8*ty;
        const float* Bb = Bc + 12*tx;

        #pragma unroll
        for (int k = 0; k < 16; ++k){
            ulonglong2 a0 = *reinterpret_cast<const ulonglong2*>(Ab + k*SA);      // rows 0-3
            ulonglong2 a1 = *reinterpret_cast<const ulonglong2*>(Ab + k*SA + 4);  // rows 4-7
            float4 b0 = *reinterpret_cast<const float4*>(Bb + k*BSTR);
            float4 b1 = *reinterpret_cast<const float4*>(Bb + k*BSTR + 4);
            unsigned long long bb0 = pack2(b0.x), bb1 = pack2(b0.y);
            unsigned long long bb2 = pack2(b0.z), bb3 = pack2(b0.w);
            unsigned long long bb4 = pack2(b1.x), bb5 = pack2(b1.y);
            unsigned long long bb6 = pack2(b1.z), bb7 = pack2(b1.w);
            ffma2(acc[0][0], a0.x, bb0); ffma2(acc[1][0], a0.y, bb0);
            ffma2(acc[2][0], a1.x, bb0); ffma2(acc[3][0], a1.y, bb0);
            ffma2(acc[0][1], a0.x, bb1); ffma2(acc[1][1], a0.y, bb1);
            ffma2(acc[2][1], a1.x, bb1); ffma2(acc[3][1], a1.y, bb1);
            ffma2(acc[0][2], a0.x, bb2); ffma2(acc[1][2], a0.y, bb2);
            ffma2(acc[2][2], a1.x, bb2); ffma2(acc[3][2], a1.y, bb2);
            ffma2(acc[0][3], a0.x, bb3); ffma2(acc[1][3], a0.y, bb3);
            ffma2(acc[2][3], a1.x, bb3); ffma2(acc[3][3], a1.y, bb3);
            ffma2(acc[0][4], a0.x, bb4); ffma2(acc[1][4], a0.y, bb4);
            ffma2(acc[2][4], a1.x, bb4); ffma2(acc[3][4], a1.y, bb4);
            ffma2(acc[0][5], a0.x, bb5); ffma2(acc[1][5], a0.y, bb5);
            ffma2(acc[2][5], a1.x, bb5); ffma2(acc[3][5], a1.y, bb5);
            ffma2(acc[0][6], a0.x, bb6); ffma2(acc[1][6], a0.y, bb6);
            ffma2(acc[2][6], a1.x, bb6); ffma2(acc[3][6], a1.y, bb6);
            ffma2(acc[0][7], a0.x, bb7); ffma2(acc[1][7], a0.y, bb7);
            ffma2(acc[2][7], a1.x, bb7); ffma2(acc[3][7], a1.y, bb7);
        }

        // drain staged regs into the other buffer
        if (it + 1 < 64){
            float* Bn = ((it+1) & 1) ? B1 : B0;
            Bn[(4*pks0+0)*BSTR + bc0] = pre0.x;  Bn[(4*pks0+1)*BSTR + bc0] = pre0.y;
            Bn[(4*pks0+2)*BSTR + bc0] = pre0.z;  Bn[(4*pks0+3)*BSTR + bc0] = pre0.w;
            Bn[(4*pks1+0)*BSTR + bc1] = pre1.x;  Bn[(4*pks1+1)*BSTR + bc1] = pre1.y;
            Bn[(4*pks1+2)*BSTR + bc1] = pre1.z;  Bn[(4*pks1+3)*BSTR + bc1] = pre1.w;
        }

        // chunk end: fold acc into running argmax (strict > keeps lowest idx)
        if (kc == 7){
            int n0 = qb + c*128 + 8*tx;
            #pragma unroll
            for (int p = 0; p < 4; ++p)
                #pragma unroll
                for (int j = 0; j < 8; ++j){
                    float2 v = unpack2(acc[p][j]);
                    if (v.x > bestv[2*p])   { bestv[2*p]   = v.x; besti[2*p]   = n0 + j; }
                    if (v.y > bestv[2*p+1]) { bestv[2*p+1] = v.y; besti[2*p+1] = n0 + j; }
                }
        }
        __syncthreads();
    }

    // Cross-thread reduction: 16 tx candidates per row; max, tie -> lower idx
    float* rv = sm;                                    // 128*16 floats
    int*   ri = reinterpret_cast<int*>(sm + 128*16);   // 128*16 ints
    #pragma unroll
    for (int i = 0; i < 8; ++i){
        int row = 8*ty + i;
        rv[row*16 + tx] = bestv[i];
        ri[row*16 + tx] = besti[i];
    }
    __syncthreads();
    if (tid < 128){
        float bv = rv[tid*16]; int bi = ri[tid*16];
        #pragma unroll
        for (int t2 = 1; t2 < 16; ++t2){
            float v = rv[tid*16 + t2]; int id = ri[tid*16 + t2];
            if (v > bv || (v == bv && id < bi)) { bv = v; bi = id; }
        }
        int m = m0 + tid;
        g_pb[((size_t)m*Qz + q)*4 + qt] = make_float2(bv, __int_as_float(bi));
    }
}

// ---------------- Kernel 4: merge quarters + gather + output rmsnorm --------
__global__ void out_kernel(const float* __restrict__ cb,
                           const float* __restrict__ w,
                           float* __restrict__ out,
                           float* __restrict__ tail){
    int m = blockIdx.x, t = threadIdx.x;
    __shared__ int   sidx[8];
    __shared__ float s_scale;
    if (t < 8){
        // merge 4 column-quarter partials (quarters ascend -> tie to lower idx)
        const float2* pb = g_pb + ((size_t)m*Qz + t)*4;
        float2 p0 = pb[0];
        float bv = p0.x; int bi = __float_as_int(p0.y);
        #pragma unroll
        for (int qt = 1; qt < 4; ++qt){
            float2 p = pb[qt];
            int id = __float_as_int(p.y);
            if (p.x > bv || (p.x == bv && id < bi)) { bv = p.x; bi = id; }
        }
        sidx[t] = bi;
        if (tail) tail[m*Qz + t] = (float)bi;
    }
    __syncthreads();
    if (t < 8){
        float p = g_hc2[t*Kz + sidx[t]];
        #pragma unroll
        for (int o = 4; o > 0; o >>= 1) p += __shfl_xor_sync(0xffu, p, o);
        if (t == 0){
            float mean = (2.0f*p) * (1.0f/1024.0f) + 1e-5f;
            float r = rsqrtf(mean);
            r = r * (1.5f - 0.5f*mean*r*r);
            s_scale = r;
        }
    }
    __syncthreads();
    int q = t >> 5, lane = t & 31;
    float4 c = reinterpret_cast<const float4*>(cb)[((size_t)q*Kz + sidx[q])*32 + lane];
    float sc = s_scale;
    float4 wv = reinterpret_cast<const float4*>(w)[t];
    reinterpret_cast<float4*>(out)[(size_t)m*256 + t] =
        make_float4(c.x*sc*wv.x, c.y*sc*wv.y, c.z*sc*wv.z, c.w*sc*wv.w);
}

// ---------------- Launch ----------------
extern "C" void kernel_launch(void* const* d_in, const int* in_sizes, int n_in,
                              void* d_out, int out_size){
    const float* x     = (const float*)d_in[0];
    const float* cb    = (const float*)d_in[1];
    const float* w_in  = (const float*)d_in[2];
    const float* w_out = (const float*)d_in[3];
    float* out = (float*)d_out;
    float* tail = (out_size >= OUT_ELEMS + IDX_ELEMS) ? (out + OUT_ELEMS) : nullptr;

    cudaFuncSetAttribute((const void*)argmin_kernel,
                         cudaFuncAttributeMaxDynamicSharedMemorySize, SMEM_ARGMIN);

    rmsnorm_in_kernel<<<Mz, 256>>>(x, w_in);
    hc2_kernel<<<(Qz*Kz)/8, 256>>>(cb);
    argmin_kernel<<<dim3((Mz/128)*4, Qz), 256, SMEM_ARGMIN>>>(cb);
    out_kernel<<<Mz, 256>>>(cb, w_out, out, tail);
}